// round 11
// baseline (speedup 1.0000x reference)
#include <cuda_runtime.h>
#include <cstdint>

#define NTOK   8192              // B*S
#define T_SLOT 16
#define E_DIM  1024
#define D_DIM  100
#define OUT_W  (E_DIM + D_DIM)   // 1124

// 256-bit (v8.b32) non-coherent global load; p must be 32B-aligned
__device__ __forceinline__ void ldg256(const float* p, float* v)
{
    asm volatile("ld.global.nc.v8.b32 {%0,%1,%2,%3,%4,%5,%6,%7}, [%8];"
                 : "=f"(v[0]), "=f"(v[1]), "=f"(v[2]), "=f"(v[3]),
                   "=f"(v[4]), "=f"(v[5]), "=f"(v[6]), "=f"(v[7])
                 : "l"(p));
}

__global__ __launch_bounds__(256)
void fuse_triples_v8_kernel(const int*   __restrict__ inputs,   // [NTOK]
                            const int*   __restrict__ triples,  // [NTOK,T,3]
                            const int*   __restrict__ flags,    // [NTOK,T]
                            const float* __restrict__ emb,      // [VOCAB,1024]
                            const float* __restrict__ ent,      // [ENT_VOCAB,100]
                            float*       __restrict__ out)      // [NTOK,1124]
{
    const int gwarp = (blockIdx.x * blockDim.x + threadIdx.x) >> 5;
    const int lane  = threadIdx.x & 31;
    const int token = gwarp;

    // ---- decode triple slots, one slot per lane (lanes 0..15) ----
    int e = -1;
    if (lane < T_SLOT) {
        const int f = flags[token * T_SLOT + lane];
        if (f == 1)      e = triples[(token * T_SLOT + lane) * 3 + 1]; // tail
        else if (f == 2) e = triples[(token * T_SLOT + lane) * 3 + 0]; // head
    }
    const unsigned vmask = __ballot_sync(0xffffffffu, e >= 0);
    const int cnt = __popc(vmask & 0xFFFFu);

    const int vrow = inputs[token];

    // ---- broadcast indices so gather loads issue back-to-back ----
    int ej[T_SLOT];
    #pragma unroll
    for (int j = 0; j < T_SLOT; ++j)
        ej[j] = __shfl_sync(0xffffffffu, e, j);

    // ---- entity gather + average: lanes 0..24 own one float4 group ----
    float4 acc = make_float4(0.f, 0.f, 0.f, 0.f);
    #pragma unroll
    for (int j = 0; j < T_SLOT; ++j) {
        if (ej[j] >= 0 && lane < 25) {
            const float4 r = reinterpret_cast<const float4*>(
                                 ent + (size_t)ej[j] * D_DIM)[lane];
            acc.x += r.x; acc.y += r.y; acc.z += r.z; acc.w += r.w;
        }
    }
    if (lane < 25) {
        const float inv = 1.0f / (float)(cnt > 0 ? cnt : 1);
        acc.x *= inv; acc.y *= inv; acc.z *= inv; acc.w *= inv;
        __stcs(reinterpret_cast<float4*>(out + (size_t)token * OUT_W + E_DIM) + lane,
               acc);
    }

    // ---- token embedding copy: 4 x 256-bit loads, 8 x 128-bit .cs stores ----
    const float* __restrict__ src = emb + (size_t)vrow * E_DIM;   // 4KB aligned
    float4* __restrict__ dst =
        reinterpret_cast<float4*>(out + (size_t)token * OUT_W);   // 16B aligned
    #pragma unroll
    for (int i = 0; i < 4; ++i) {
        float v[8];
        ldg256(src + (size_t)(lane + 32 * i) * 8, v);             // 32B aligned
        __stcs(dst + (lane + 32 * i) * 2,
               make_float4(v[0], v[1], v[2], v[3]));
        __stcs(dst + (lane + 32 * i) * 2 + 1,
               make_float4(v[4], v[5], v[6], v[7]));
    }
}

extern "C" void kernel_launch(void* const* d_in, const int* in_sizes, int n_in,
                              void* d_out, int out_size)
{
    const int*   inputs  = (const int*)  d_in[0];
    const int*   triples = (const int*)  d_in[1];
    const int*   flags   = (const int*)  d_in[2];
    const float* emb     = (const float*)d_in[3];
    const float* ent     = (const float*)d_in[4];
    float*       out     = (float*)      d_out;

    // one warp per token: 8192 warps = 1024 blocks * 8 warps
    fuse_triples_v8_kernel<<<NTOK / 8, 256>>>(inputs, triples, flags, emb, ent, out);
}

// round 12
// speedup vs baseline: 1.4199x; 1.4199x over previous
#include <cuda_runtime.h>
#include <cstdint>

#define NTOK   8192              // B*S
#define T_SLOT 16
#define E_DIM  1024
#define D_DIM  100
#define OUT_W  (E_DIM + D_DIM)   // 1124

__global__ __launch_bounds__(128)
void fuse_triples_flat_kernel(const int*   __restrict__ inputs,   // [NTOK]
                              const int*   __restrict__ triples,  // [NTOK,T,3]
                              const int*   __restrict__ flags,    // [NTOK,T]
                              const float* __restrict__ emb,      // [VOCAB,1024]
                              const float* __restrict__ ent,      // [ENT_VOCAB,100]
                              float*       __restrict__ out)      // [NTOK,1124]
{
    const int gwarp = (blockIdx.x * blockDim.x + threadIdx.x) >> 5;
    const int lane  = threadIdx.x & 31;
    const int token = gwarp;

    // ---- hop 1: ALL independent loads issued together ----
    const int vrow = inputs[token];                       // token row id

    int f  = 0, t0 = 0, t1 = 0;
    if (lane < T_SLOT) {
        const int slot = token * T_SLOT + lane;
        f  = flags[slot];                                 // flag
        t0 = triples[slot * 3 + 0];                       // head (unconditional)
        t1 = triples[slot * 3 + 1];                       // tail (unconditional)
    }

    // copy loads depend only on vrow — issue before the gather decode
    const float4* __restrict__ src =
        reinterpret_cast<const float4*>(emb + (size_t)vrow * E_DIM);
    float4 c[8];
    #pragma unroll
    for (int i = 0; i < 8; ++i)
        c[i] = src[lane + 32 * i];

    // ---- ALU-only decode (no second memory hop) ----
    int e = -1;
    if (lane < T_SLOT) {
        if (f == 1)      e = t1;   // tail entity
        else if (f == 2) e = t0;   // head entity
    }
    const unsigned vmask = __ballot_sync(0xffffffffu, e >= 0);
    const int cnt = __popc(vmask & 0xFFFFu);

    int ej[T_SLOT];
    #pragma unroll
    for (int j = 0; j < T_SLOT; ++j)
        ej[j] = __shfl_sync(0xffffffffu, e, j);

    // ---- hop 2: entity gathers (lanes 0..24, one float4 each) ----
    float4 acc = make_float4(0.f, 0.f, 0.f, 0.f);
    #pragma unroll
    for (int j = 0; j < T_SLOT; ++j) {
        if (ej[j] >= 0 && lane < 25) {
            const float4 r = reinterpret_cast<const float4*>(
                                 ent + (size_t)ej[j] * D_DIM)[lane];
            acc.x += r.x; acc.y += r.y; acc.z += r.z; acc.w += r.w;
        }
    }

    // ---- stores (all .cs: keep output out of L2's protected set) ----
    float4* __restrict__ dst =
        reinterpret_cast<float4*>(out + (size_t)token * OUT_W);
    #pragma unroll
    for (int i = 0; i < 8; ++i)
        __stcs(dst + lane + 32 * i, c[i]);

    if (lane < 25) {
        const float inv = 1.0f / (float)(cnt > 0 ? cnt : 1);
        acc.x *= inv; acc.y *= inv; acc.z *= inv; acc.w *= inv;
        __stcs(reinterpret_cast<float4*>(out + (size_t)token * OUT_W + E_DIM) + lane,
               acc);
    }
}

extern "C" void kernel_launch(void* const* d_in, const int* in_sizes, int n_in,
                              void* d_out, int out_size)
{
    const int*   inputs  = (const int*)  d_in[0];
    const int*   triples = (const int*)  d_in[1];
    const int*   flags   = (const int*)  d_in[2];
    const float* emb     = (const float*)d_in[3];
    const float* ent     = (const float*)d_in[4];
    float*       out     = (float*)      d_out;

    // one warp per token: 8192 warps = 2048 blocks * 4 warps
    fuse_triples_flat_kernel<<<NTOK / 4, 128>>>(inputs, triples, flags,
                                                emb, ent, out);
}